// round 2
// baseline (speedup 1.0000x reference)
#include <cuda_runtime.h>

// Integrate-and-fire: per neuron (b,h,w,c), scan t: v += x; if (v > 2) {spike=1; v=0}
// v resets at chunk boundary t==100. out[b,t,w,c,h] = spike[b,h,w,c,t].
//
// Input  index: b*6553600 + t*32768 + h*512 + w*8 + c
// Output index: b*6553600 + t*32768 + w*512 + c*64 + h

#define T_TOTAL  200
#define WINDOW_T 100
#define STRIDE_T 32768      // 64*64*8
#define STRIDE_B 6553600    // 200*STRIDE_T
#define VM_THR   2.0f

__global__ __launch_bounds__(512)
void iaf_kernel(const float* __restrict__ in, float* __restrict__ out) {
    const int w   = blockIdx.x;          // 0..63
    const int b   = blockIdx.y;          // 0..3
    const int tid = threadIdx.x;         // 0..511
    const int h   = tid >> 3;            // 0..63
    const int c   = tid & 7;             // 0..7

    const float* ip = in  + (size_t)b * STRIDE_B + h * 512 + w * 8 + c;
    float*       op = out + (size_t)b * STRIDE_B + w * 512 + c * 64 + h;

    constexpr int U = 8;
    float cur[U], nxt[U];

    // prime the pipeline
    #pragma unroll
    for (int k = 0; k < U; k++) cur[k] = ip[k * STRIDE_T];

    float v = 0.0f;
    for (int t0 = 0; t0 < T_TOTAL; t0 += U) {
        // prefetch next batch (overlaps with compute + stores below)
        if (t0 + U < T_TOTAL) {
            #pragma unroll
            for (int k = 0; k < U; k++) nxt[k] = ip[(t0 + U + k) * STRIDE_T];
        }
        // sequential integrate-and-fire on current batch
        #pragma unroll
        for (int k = 0; k < U; k++) {
            if (t0 + k == WINDOW_T) v = 0.0f;   // chunk boundary reset
            v += cur[k];
            float s = 0.0f;
            if (v > VM_THR) { s = 1.0f; v = 0.0f; }
            op[(t0 + k) * STRIDE_T] = s;
        }
        #pragma unroll
        for (int k = 0; k < U; k++) cur[k] = nxt[k];
    }
}

extern "C" void kernel_launch(void* const* d_in, const int* in_sizes, int n_in,
                              void* d_out, int out_size) {
    const float* in = (const float*)d_in[0];
    float* out = (float*)d_out;
    dim3 grid(64, 4);   // (w, b)
    iaf_kernel<<<grid, 512>>>(in, out);
}

// round 3
// speedup vs baseline: 1.6671x; 1.6671x over previous
#include <cuda_runtime.h>

// Integrate-and-fire: per neuron (b,h,w,c), scan t: v += x; if (v > 2) {spike=1; v=0}
// v resets at chunk boundary t==100 -> the two 100-step chunks are fully
// independent => parallelize over chunks (blockIdx.z).
//
// Input  index: b*6553600 + t*32768 + h*512 + w*8 + c   (coalesced per warp)
// Output index: b*6553600 + t*32768 + w*512 + (c*64+h)  (transposed via smem
//               so global stores are 128B-coalesced: thread tid writes
//               linear offset w*512 + tid)

#define T_CHUNK  100
#define STRIDE_T 32768      // 64*64*8
#define STRIDE_B 6553600    // 200*STRIDE_T
#define VM_THR   2.0f
#define U        5          // double-buffer depth; 100 % U == 0

__global__ __launch_bounds__(512, 4)
void iaf_kernel(const float* __restrict__ in, float* __restrict__ out) {
    const int w     = blockIdx.x;        // 0..63
    const int b     = blockIdx.y;        // 0..3
    const int chunk = blockIdx.z;        // 0..1  (independent 100-step windows)
    const int tid   = threadIdx.x;       // 0..511
    const int h     = tid >> 3;          // 0..63  (input-side mapping)
    const int c     = tid & 7;           // 0..7

    // smem staging: s[k][h*9 + c]; pad-9 makes the transposed read
    // (stride-9 across a warp) bank-conflict-free.
    __shared__ float s[U][64 * 9];

    const size_t base = (size_t)b * STRIDE_B + (size_t)chunk * T_CHUNK * STRIDE_T;
    const float* ip = in  + base + h * 512 + w * 8 + c;
    float*       op = out + base + w * 512 + tid;           // output-linear: tid == c_o*64 + h_o
    const int sread = (tid & 63) * 9 + (tid >> 6);          // inverse map into smem

    float cur[U], nxt[U];
    #pragma unroll
    for (int k = 0; k < U; k++) cur[k] = ip[k * STRIDE_T];

    float v = 0.0f;
    for (int t0 = 0; t0 < T_CHUNK; t0 += U) {
        // prefetch next batch (overlaps the scan + smem + stores)
        if (t0 + U < T_CHUNK) {
            #pragma unroll
            for (int k = 0; k < U; k++) nxt[k] = ip[(t0 + U + k) * STRIDE_T];
        }
        // sequential integrate-and-fire; spikes staged to smem
        #pragma unroll
        for (int k = 0; k < U; k++) {
            v += cur[k];
            float sp = 0.0f;
            if (v > VM_THR) { sp = 1.0f; v = 0.0f; }
            s[k][h * 9 + c] = sp;
        }
        __syncthreads();
        // coalesced 128B stores through the transposed view
        #pragma unroll
        for (int k = 0; k < U; k++) op[(t0 + k) * STRIDE_T] = s[k][sread];
        __syncthreads();
        #pragma unroll
        for (int k = 0; k < U; k++) cur[k] = nxt[k];
    }
}

extern "C" void kernel_launch(void* const* d_in, const int* in_sizes, int n_in,
                              void* d_out, int out_size) {
    const float* in = (const float*)d_in[0];
    float* out = (float*)d_out;
    dim3 grid(64, 4, 2);   // (w, b, chunk)
    iaf_kernel<<<grid, 512>>>(in, out);
}

// round 4
// speedup vs baseline: 1.7313x; 1.0385x over previous
#include <cuda_runtime.h>

// Integrate-and-fire: per neuron (b,h,w,c), scan t: v += x; if (v > 2) {spike=1; v=0}
// v resets at chunk boundary t==100 -> the two 100-step chunks are independent
// => parallelize over chunks. h is further split in half for finer block
// granularity (1024 blocks -> ~86% occupancy vs 67% at 512 blocks).
//
// Input  index: b*6553600 + t*32768 + h*512 + w*8 + c   (coalesced per warp)
// Output index: b*6553600 + t*32768 + w*512 + (c*64+h)  (transposed via smem;
//               per warp c is fixed, h-low spans 32 -> 128B coalesced stores)

#define T_CHUNK  100
#define STRIDE_T 32768      // 64*64*8
#define STRIDE_B 6553600    // 200*STRIDE_T
#define VM_THR   2.0f
#define U        5          // double-buffer depth; 100 % U == 0

__global__ __launch_bounds__(256, 8)
void iaf_kernel(const float* __restrict__ in, float* __restrict__ out) {
    const int wx    = blockIdx.x;        // 0..127 : w*2 + h-half
    const int w     = wx >> 1;           // 0..63
    const int hh    = wx & 1;            // 0..1   (h half)
    const int b     = blockIdx.y;        // 0..3
    const int chunk = blockIdx.z;        // 0..1
    const int tid   = threadIdx.x;       // 0..255
    const int hl    = tid >> 3;          // 0..31  (h within half)
    const int c     = tid & 7;           // 0..7
    const int h     = hh * 32 + hl;

    // smem staging: s[k][hl*9 + c]; pad-9 => transposed read (stride 9, 9⊥32)
    // is bank-conflict-free.
    __shared__ float s[U][32 * 9];

    const size_t base = (size_t)b * STRIDE_B + (size_t)chunk * T_CHUNK * STRIDE_T;
    const float* ip = in  + base + h * 512 + w * 8 + c;
    // store mapping: thread tid -> output linear w*512 + (tid>>5)*64 + hh*32 + (tid&31)
    float*       op = out + base + w * 512 + (tid >> 5) * 64 + hh * 32 + (tid & 31);
    const int sread = (tid & 31) * 9 + (tid >> 5);   // smem[hl'][c'] for that output slot

    float cur[U], nxt[U];
    #pragma unroll
    for (int k = 0; k < U; k++) cur[k] = ip[k * STRIDE_T];

    float v = 0.0f;
    for (int t0 = 0; t0 < T_CHUNK; t0 += U) {
        // prefetch next batch (in flight across scan + transpose + stores)
        if (t0 + U < T_CHUNK) {
            #pragma unroll
            for (int k = 0; k < U; k++) nxt[k] = ip[(t0 + U + k) * STRIDE_T];
        }
        // sequential integrate-and-fire; spikes staged to smem
        #pragma unroll
        for (int k = 0; k < U; k++) {
            v += cur[k];
            float sp = 0.0f;
            if (v > VM_THR) { sp = 1.0f; v = 0.0f; }
            s[k][hl * 9 + c] = sp;
        }
        __syncthreads();
        // coalesced 128B stores through the transposed view
        #pragma unroll
        for (int k = 0; k < U; k++) op[(t0 + k) * STRIDE_T] = s[k][sread];
        __syncthreads();
        #pragma unroll
        for (int k = 0; k < U; k++) cur[k] = nxt[k];
    }
}

extern "C" void kernel_launch(void* const* d_in, const int* in_sizes, int n_in,
                              void* d_out, int out_size) {
    const float* in = (const float*)d_in[0];
    float* out = (float*)d_out;
    dim3 grid(128, 4, 2);   // (w*2+hhalf, b, chunk)
    iaf_kernel<<<grid, 256>>>(in, out);
}

// round 5
// speedup vs baseline: 2.0411x; 1.1789x over previous
#include <cuda_runtime.h>

// Integrate-and-fire: per neuron (b,h,w,c), scan t: v += x; if (v > 2) {spike=1; v=0}
// Two independent 100-step windows (v resets at t==100) -> chunk parallelism.
//
// Block = 4w x 32h x 8c = 1024 neurons, so BOTH memory phases use full
// 128B lines per warp:
//   input : warp = fixed h, lane = wl*8+c  -> 32 consecutive floats
//   output: warp = fixed (w,c), lane = h   -> 32 consecutive floats
// Spikes cross the (h <-> w,c) transpose through pad-33 smem (conflict-free
// both ways), double-buffered so only ONE __syncthreads per 5-step batch.
//
// Input  index: b*6553600 + t*32768 + h*512 + w*8 + c
// Output index: b*6553600 + t*32768 + w*512 + c*64 + h

#define T_CHUNK  100
#define STRIDE_T 32768      // 64*64*8
#define STRIDE_B 6553600    // 200*STRIDE_T
#define VM_THR   2.0f
#define U        5          // batch depth; 100 % U == 0

__global__ __launch_bounds__(1024, 2)
void iaf_kernel(const float* __restrict__ in, float* __restrict__ out) {
    const int wt    = blockIdx.x >> 1;   // 0..15  (w tile of 4)
    const int hh    = blockIdx.x & 1;    // 0..1   (h half of 32)
    const int b     = blockIdx.y;        // 0..3
    const int chunk = blockIdx.z;        // 0..1
    const int tid   = threadIdx.x;       // 0..1023

    // transpose staging, double-buffered; row pad 33 (33 ⊥ 32) kills bank
    // conflicts on the strided side.
    __shared__ float sbuf[2][U][32 * 33];

    const int hloc = tid >> 5;           // 0..31 (input-role h)
    const int lane = tid & 31;           // input-role: wl*8+c

    const size_t base = (size_t)b * STRIDE_B + (size_t)chunk * T_CHUNK * STRIDE_T;
    const float* ip = in  + base + (size_t)(hh * 32 + hloc) * 512 + wt * 32 + lane;

    // output role: tid -> (wl'=tid>>8, c'=(tid>>5)&7, h'=lane)
    const int wl_o = tid >> 8;
    const int c_o  = (tid >> 5) & 7;
    float* op = out + base + (size_t)wt * 2048 + wl_o * 512 + c_o * 64 + hh * 32 + lane;

    const int swr = hloc * 33 + lane;            // write: lane stride 1
    const int srd = lane * 33 + wl_o * 8 + c_o;  // read : lane stride 33 (conflict-free)

    float cur[U], nxt[U];
    #pragma unroll
    for (int k = 0; k < U; k++) cur[k] = __ldcs(ip + k * STRIDE_T);

    float v = 0.0f;
    int buf = 0;
    for (int t0 = 0; t0 < T_CHUNK; t0 += U, buf ^= 1) {
        // prefetch next batch (in flight across scan + transpose + stores)
        if (t0 + U < T_CHUNK) {
            #pragma unroll
            for (int k = 0; k < U; k++) nxt[k] = __ldcs(ip + (t0 + U + k) * STRIDE_T);
        }
        // sequential integrate-and-fire; spikes staged to smem
        #pragma unroll
        for (int k = 0; k < U; k++) {
            v += cur[k];
            float sp = 0.0f;
            if (v > VM_THR) { sp = 1.0f; v = 0.0f; }
            sbuf[buf][k][swr] = sp;
        }
        __syncthreads();   // writes(buf) done; prior-iteration reads(buf^1) also done
        // fully-coalesced 128B stores through the transposed role
        #pragma unroll
        for (int k = 0; k < U; k++) __stcs(op + (t0 + k) * STRIDE_T, sbuf[buf][k][srd]);
        #pragma unroll
        for (int k = 0; k < U; k++) cur[k] = nxt[k];
    }
}

extern "C" void kernel_launch(void* const* d_in, const int* in_sizes, int n_in,
                              void* d_out, int out_size) {
    const float* in = (const float*)d_in[0];
    float* out = (float*)d_out;
    dim3 grid(32, 4, 2);   // (wt*2+hh, b, chunk)
    iaf_kernel<<<grid, 1024>>>(in, out);
}